// round 15
// baseline (speedup 1.0000x reference)
#include <cuda_runtime.h>
#include <cstdint>

// MultiGaussianReadoutLayer fused kernel, R13.
// B=32, O=12000, F_IN=64, F_OUT=4, M=16.
//
// R13 = R11 with a QUARTER-split mainloop: lane=(quarter,bq) owns 4 sig
// outputs + 1 mu for 4 b-rows {bq,bq+8,bq+16,bq+24}. Weight smem return
// drops to 20B/lane/f: sig 1xLDS.128 + mu 1xLDS.32 + x float4-of-f
// => 9 wavefronts/warp/f vs R11's 12 (return-BW model: 1152B vs 1536B).
// x tile [o][b][f] (o-stride 644, b-stride 20): conflict-free STS.128
// staging and conflict-free LDS.128 reads. Exchange/eps stages = R11.

#define B_    32
#define O_    12000
#define FIN   64
#define M_    16
#define OB    8
#define NT    256
#define FQ    16            // f per staged chunk (4 chunks)
#define NQ    (FIN / FQ)    // 4
#define BSTR  20            // x-tile b-stride (16 f + 4 pad); bq*20 mod 32 distinct
#define OSTR  644           // x-tile o-stride (32*20 + 4)
#define EX_BS 164           // exchange b-stride (floats)
#define EX_OS 20            // exchange o-stride (floats)

#define SW_OFF 0
#define MW_OFF (OB * 1024)                       // 8192
#define SB_OFF (MW_OFF + OB * 256)               // 10240
#define MB_OFF (SB_OFF + OB * 16)                // 10368
#define SX_OFF (MB_OFF + OB * 4)                 // 10400
#define SMEM_FLOATS (SX_OFF + OB * OSTR)         // 15552 floats = 62208 B

__device__ __forceinline__ uint64_t pack2(float lo, float hi) {
    uint64_t r; asm("mov.b64 %0, {%1,%2};" : "=l"(r) : "f"(lo), "f"(hi)); return r;
}
__device__ __forceinline__ uint64_t ffma2(uint64_t a, uint64_t b, uint64_t c) {
    uint64_t d; asm("fma.rn.f32x2 %0, %1, %2, %3;" : "=l"(d) : "l"(a), "l"(b), "l"(c));
    return d;
}
__device__ __forceinline__ void unpack2(uint64_t v, float& lo, float& hi) {
    asm("mov.b64 {%0,%1}, %2;" : "=f"(lo), "=f"(hi) : "l"(v));
}

__global__ void __launch_bounds__(NT, 3)
mgr_kernel(const float* __restrict__ x,
           const float* __restrict__ mu_w,
           const float* __restrict__ mu_b,
           const float* __restrict__ sigma_w,
           const float* __restrict__ sigma_b,
           const float* __restrict__ eps,
           float* __restrict__ out)
{
    extern __shared__ __align__(16) float smem[];
    float* sw = smem + SW_OFF;
    float* mw = smem + MW_OFF;
    float* sb = smem + SB_OFF;
    float* mb = smem + MB_OFF;
    float* sx = smem + SX_OFF;

    const int tid    = threadIdx.x;
    const int o_base = blockIdx.x * OB;

    // ---- stage weights + biases (coalesced float4, linear smem) ----
    {
        const float4* src_s = (const float4*)(sigma_w + (size_t)o_base * 1024);
        #pragma unroll
        for (int i = tid; i < OB * 256; i += NT)
            ((float4*)sw)[i] = src_s[i];
        const float4* src_m = (const float4*)(mu_w + (size_t)o_base * 256);
        #pragma unroll
        for (int i = tid; i < OB * 64; i += NT)
            ((float4*)mw)[i] = src_m[i];
        if (tid < OB * 16) sb[tid] = sigma_b[(size_t)o_base * 16 + tid];
        if (tid < OB * 4)  mb[tid] = mu_b[(size_t)o_base * 4 + tid];
    }

    // mainloop mapping: warp <-> instance; lane = (quarter, bq)
    const int o_w     = tid >> 5;      // 0..7
    const int lane    = tid & 31;
    const int quarter = lane >> 3;     // owns sig[4q..4q+3] + mu[q]
    const int bq      = lane & 7;      // b = bq + 8g, g = 0..3

    const float* swp   = sw + o_w * 1024 + quarter * 4;
    const float* mwp   = mw + o_w * 256 + quarter;
    const float* xbase = sx + o_w * OSTR + bq * BSTR;

    // accumulators: per g (b-row): 2 packed sig pairs + 1 scalar mu
    uint64_t s0[4], s1[4];
    float    mq[4];

    // staging decomposition: lane = f4l*8 + o within warp -> STS.128 phases
    // have fixed f4l, varying o => conflict-free.
    // i = b*32 + f4l*8 + o
    #pragma unroll
    for (int q = 0; q < NQ; q++) {
        #pragma unroll
        for (int i = tid; i < B_ * OB * (FQ / 4); i += NT) {   // 1024 float4
            int o   = i & 7;
            int f4l = (i >> 3) & 3;
            int b   = i >> 5;
            float4 v = ((const float4*)x)[((size_t)b * O_ + o_base + o) * 16 + q * 4 + f4l];
            *(float4*)(sx + o * OSTR + b * BSTR + f4l * 4) = v;
        }
        __syncthreads();

        if (q == 0) {   // init AFTER first sync: sb/mb visible (race fix)
            #pragma unroll
            for (int g = 0; g < 4; g++) {
                s0[g] = pack2(sb[o_w * 16 + quarter * 4 + 0],
                              sb[o_w * 16 + quarter * 4 + 1]);
                s1[g] = pack2(sb[o_w * 16 + quarter * 4 + 2],
                              sb[o_w * 16 + quarter * 4 + 3]);
                mq[g] = mb[o_w * 4 + quarter];
            }
        }

        #pragma unroll
        for (int fg = 0; fg < FQ / 4; fg++) {
            // x for 4 b-rows, 4 consecutive f each (conflict-free LDS.128)
            float4 xg0 = *(const float4*)(xbase + 0 * 8 * BSTR + fg * 4);
            float4 xg1 = *(const float4*)(xbase + 1 * 8 * BSTR + fg * 4);
            float4 xg2 = *(const float4*)(xbase + 2 * 8 * BSTR + fg * 4);
            float4 xg3 = *(const float4*)(xbase + 3 * 8 * BSTR + fg * 4);

            #pragma unroll
            for (int j = 0; j < 4; j++) {
                const int f = q * FQ + fg * 4 + j;
                // this quarter's weights: 4 sig floats + 1 mu float
                ulonglong2 sv = *(const ulonglong2*)(swp + f * 16);
                const float wm = mwp[f * 4];

                const float xf0 = (j==0)?xg0.x:(j==1)?xg0.y:(j==2)?xg0.z:xg0.w;
                const float xf1 = (j==0)?xg1.x:(j==1)?xg1.y:(j==2)?xg1.z:xg1.w;
                const float xf2 = (j==0)?xg2.x:(j==1)?xg2.y:(j==2)?xg2.z:xg2.w;
                const float xf3 = (j==0)?xg3.x:(j==1)?xg3.y:(j==2)?xg3.z:xg3.w;

                uint64_t xx0 = pack2(xf0, xf0);
                uint64_t xx1 = pack2(xf1, xf1);
                uint64_t xx2 = pack2(xf2, xf2);
                uint64_t xx3 = pack2(xf3, xf3);

                s0[0] = ffma2(sv.x, xx0, s0[0]);  s1[0] = ffma2(sv.y, xx0, s1[0]);
                s0[1] = ffma2(sv.x, xx1, s0[1]);  s1[1] = ffma2(sv.y, xx1, s1[1]);
                s0[2] = ffma2(sv.x, xx2, s0[2]);  s1[2] = ffma2(sv.y, xx2, s1[2]);
                s0[3] = ffma2(sv.x, xx3, s0[3]);  s1[3] = ffma2(sv.y, xx3, s1[3]);

                mq[0] = fmaf(wm, xf0, mq[0]);
                mq[1] = fmaf(wm, xf1, mq[1]);
                mq[2] = fmaf(wm, xf2, mq[2]);
                mq[3] = fmaf(wm, xf3, mq[3]);
            }
        }
        __syncthreads();
    }

    // ---- exchange sig/mu through smem (reuse dead sigma_w region) ----
    // per (b,o) slot: uint64[0..7] = sig pairs, floats[16..19] = mu[0..3]
    // quarter q writes uint64 slots 2q, 2q+1 and float 16+q.
    #pragma unroll
    for (int g = 0; g < 4; g++) {
        const int b = bq + 8 * g;
        float* exf = sw + b * EX_BS + o_w * EX_OS;
        uint64_t* ex = (uint64_t*)exf;
        ex[2 * quarter]     = s0[g];
        ex[2 * quarter + 1] = s1[g];
        exf[16 + quarter]   = mq[g];
    }
    __syncthreads();

    const int o_l = tid & (OB - 1);
    const int b   = tid >> 3;
    const int og  = o_base + o_l;

    float sig[16], mu0, mu1, mu2, mu3;
    {
        const uint64_t* exr = (const uint64_t*)(sw + b * EX_BS + o_l * EX_OS);
        #pragma unroll
        for (int j = 0; j < 8; j++)
            unpack2(exr[j], sig[2 * j], sig[2 * j + 1]);
        unpack2(exr[8], mu0, mu1);    // floats 16,17 = mu0,mu1
        unpack2(exr[9], mu2, mu3);    // floats 18,19 = mu2,mu3
    }

    uint64_t ep01[4], ep23[4];
    #pragma unroll
    for (int f = 0; f < 4; f++) {
        ep01[f] = pack2(sig[f],     sig[4 + f]);
        ep23[f] = pack2(sig[8 + f], sig[12 + f]);
    }
    const uint64_t mu01 = pack2(mu0, mu1);
    const uint64_t mu23 = pack2(mu2, mu3);

    // ---- eps application: [M, B, O, 4] float4 coalesced ----
    const size_t beo = (size_t)b * O_ + og;
    #pragma unroll
    for (int m = 0; m < M_; m++) {
        const size_t idx = ((size_t)m * B_ * O_ + beo) * 4;
        float4 e = __ldg((const float4*)(eps + idx));
        uint64_t ex = pack2(e.x, e.x), ey = pack2(e.y, e.y);
        uint64_t ez = pack2(e.z, e.z), ew = pack2(e.w, e.w);

        uint64_t p01 = ffma2(ep01[0], ex, mu01);
        p01 = ffma2(ep01[1], ey, p01);
        p01 = ffma2(ep01[2], ez, p01);
        p01 = ffma2(ep01[3], ew, p01);

        uint64_t p23 = ffma2(ep23[0], ex, mu23);
        p23 = ffma2(ep23[1], ey, p23);
        p23 = ffma2(ep23[2], ez, p23);
        p23 = ffma2(ep23[3], ew, p23);

        float4 r;
        unpack2(p01, r.x, r.y);
        unpack2(p23, r.z, r.w);
        *(float4*)(out + idx) = r;
    }
}

extern "C" void kernel_launch(void* const* d_in, const int* in_sizes, int n_in,
                              void* d_out, int out_size)
{
    const float* x       = (const float*)d_in[0];
    const float* mu_w    = (const float*)d_in[1];
    const float* mu_b    = (const float*)d_in[2];
    const float* sigma_w = (const float*)d_in[3];
    const float* sigma_b = (const float*)d_in[4];
    const float* eps     = (const float*)d_in[5];
    float* out           = (float*)d_out;

    const int smem_bytes = SMEM_FLOATS * sizeof(float);   // 62208
    cudaFuncSetAttribute(mgr_kernel,
                         cudaFuncAttributeMaxDynamicSharedMemorySize, smem_bytes);

    dim3 grid(O_ / OB);   // 1500 CTAs
    dim3 block(NT);
    mgr_kernel<<<grid, block, smem_bytes>>>(x, mu_w, mu_b, sigma_w, sigma_b, eps, out);
}